// round 4
// baseline (speedup 1.0000x reference)
#include <cuda_runtime.h>

#define S_LEN   2048
#define NCH     64
#define NB      16
#define CHUNK   128
#define NSC     (S_LEN / CHUNK)        // 16 sample-chunks
#define PLI_THREADS 512
#define NWARPS  (PLI_THREADS / 32)
#define FFT_THREADS 512
#define N_PLI_BLOCKS (NSC * NB)        // 256

// Scratch (static __device__ allocation — allowed by harness rules)
__device__ unsigned g_theta[NB * NCH * S_LEN];    // 8 MB quantized phase
__device__ int      g_cnt[NB * NCH * NCH];        // 256 KB counters
__device__ int      g_done;                       // finalize gate

// ---------------------------------------------------------------------------
// Radix-4 Stockham autosort FFT pieces (N = 2048 = 2 * 4^5).
// DIF formulation; natural-order in, natural-order out; ping-pong buffers.
// ---------------------------------------------------------------------------
__device__ __forceinline__ float2 cmul(float2 a, float2 b) {
    return make_float2(fmaf(a.x, b.x, -a.y * b.y),
                       fmaf(a.x, b.y,  a.y * b.x));
}

// radix-2 first stage (forward only): L = 1024, M = 1
__device__ __forceinline__ void stage_r2_fwd(const float2* __restrict__ src,
                                             float2* __restrict__ dst,
                                             const float2* __restrict__ tw,
                                             int tid) {
    for (int p = tid; p < 1024; p += FFT_THREADS) {
        float2 w = tw[p];                       // exp(-2*pi*i p/2048)
        float2 a = src[p];
        float2 b = src[p + 1024];
        dst[2 * p]     = make_float2(a.x + b.x, a.y + b.y);
        dst[2 * p + 1] = cmul(w, make_float2(a.x - b.x, a.y - b.y));
    }
}

// radix-4 stage: L * M * 4 == 2048
template<int L, int LOG2M, bool INV>
__device__ __forceinline__ void stage_r4(const float2* __restrict__ src,
                                         float2* __restrict__ dst,
                                         const float2* __restrict__ tw,
                                         int tid) {
    constexpr int M   = 1 << LOG2M;
    constexpr int TWS = 512 / L;                // twiddle stride
    for (int t = tid; t < 512; t += FFT_THREADS) {
        const int p = t >> LOG2M;
        const int q = t & (M - 1);
        const int ib = q + M * p;               // == t
        float2 a = src[ib];
        float2 b = src[ib + M * L];
        float2 c = src[ib + 2 * M * L];
        float2 d = src[ib + 3 * M * L];

        float2 w1 = tw[p * TWS];                // exp(-2*pi*i p/(4L))
        float2 w2 = tw[2 * p * TWS];
        if (INV) { w1.y = -w1.y; w2.y = -w2.y; }
        float2 w3 = cmul(w1, w2);

        float2 t0 = make_float2(a.x + c.x, a.y + c.y);
        float2 t1 = make_float2(a.x - c.x, a.y - c.y);
        float2 t2 = make_float2(b.x + d.x, b.y + d.y);
        float2 e  = make_float2(b.x - d.x, b.y - d.y);
        float2 t3 = INV ? make_float2(-e.y,  e.x)
                        : make_float2( e.y, -e.x);

        const int ob = q + 4 * M * p;
        dst[ob]         = make_float2(t0.x + t2.x, t0.y + t2.y);
        dst[ob + M]     = cmul(w1, make_float2(t1.x + t3.x, t1.y + t3.y));
        dst[ob + 2 * M] = cmul(w2, make_float2(t0.x - t2.x, t0.y - t2.y));
        dst[ob + 3 * M] = cmul(w3, make_float2(t1.x - t3.x, t1.y - t3.y));
    }
}

// 5 inverse radix-4 stages (after the fused stage-1). Result lands in Y.
__device__ __forceinline__ void ifft_tail(float2* __restrict__ X,
                                          float2* __restrict__ Y,
                                          const float2* __restrict__ tw,
                                          int tid) {
    stage_r4<256, 1, true>(X, Y, tw, tid);  __syncthreads();
    stage_r4< 64, 3, true>(Y, X, tw, tid);  __syncthreads();
    stage_r4< 16, 5, true>(X, Y, tw, tid);  __syncthreads();
    stage_r4<  4, 7, true>(Y, X, tw, tid);  __syncthreads();
    stage_r4<  1, 9, true>(X, Y, tw, tid);  __syncthreads();
}

// ---------------------------------------------------------------------------
// Kernel 1: Hilbert analytic signal -> quantized phase, 2 channels per block.
// z = x0 + i*x1 -> one forward FFT; unpack + Hilbert filter fused with the
// degenerate first inverse stage (spectrum zero for k > N/2); 5-stage inverse
// tails; atan2 quantized to uint32 (period 2^32 == 2*pi) so downstream sign
// tests become UNSIGNED subtract (defined wrap) + signed compare.
// Positive real scale factors (1/2, 1/N) dropped: signs are scale-invariant.
// Also zeroes g_cnt / g_done for the pli pass (stream-ordered before it).
// ---------------------------------------------------------------------------
__global__ __launch_bounds__(FFT_THREADS)
void hilbert_kernel(const float* __restrict__ x) {
    extern __shared__ float2 smem[];
    float2* A  = smem;                 // 2048
    float2* B  = smem + 2048;          // 2048
    float2* C  = smem + 4096;          // 2048
    float2* tw = smem + 6144;          // 1024

    const int tid = threadIdx.x;
    const int blk = blockIdx.x;                 // 0..511
    const int ch0 = 2 * blk;                    // global channel pair base

    // fused zeroing of counters + done flag (visible to pli via stream order)
    if (tid < 128) g_cnt[blk * 128 + tid] = 0;
    if (blk == 0 && tid == 0) g_done = 0;

    const float* __restrict__ x0 = x + (size_t)ch0 * S_LEN;
    const float* __restrict__ x1 = x0 + S_LEN;

    // twiddles tw[k] = exp(-2*pi*i k / 2048), k = 0..1023
    for (int k = tid; k < 1024; k += FFT_THREADS) {
        float sn, cs;
        sincosf((-6.283185307179586f / 2048.0f) * (float)k, &sn, &cs);
        tw[k] = make_float2(cs, sn);
    }
    for (int i = tid; i < S_LEN; i += FFT_THREADS)
        A[i] = make_float2(x0[i], x1[i]);
    __syncthreads();

    // forward FFT: result in A (natural order)
    stage_r2_fwd(A, B, tw, tid);               __syncthreads();
    stage_r4<256, 1, false>(B, A, tw, tid);    __syncthreads();
    stage_r4< 64, 3, false>(A, B, tw, tid);    __syncthreads();
    stage_r4< 16, 5, false>(B, A, tw, tid);    __syncthreads();
    stage_r4<  4, 7, false>(A, B, tw, tid);    __syncthreads();
    stage_r4<  1, 9, false>(B, A, tw, tid);    __syncthreads();

    // Unpack + Hilbert filter + fused inverse stage-1.
    //   G0[k] = h[k]*(Z[k] + conj(Z[N-k]))        (ch0 spectrum)
    //   G1[k] = h[k]*(-i)*(Z[k] - conj(Z[N-k]))   (ch1 spectrum)
    // Both zero for k > N/2, so inverse stage-1 (radix-2) degenerates:
    //   p>=1 : dst[2p] = G[p], dst[2p+1] = conj(w_p)*G[p]
    //   p==0 : dst[0] = G[0]+G[1024], dst[1] = G[0]-G[1024]
    for (int p = tid; p < 1024; p += FFT_THREADS) {
        float2 zk = A[p];
        float2 zm = A[(S_LEN - p) & (S_LEN - 1)];
        float  h  = (p == 0) ? 1.0f : 2.0f;
        float2 G0 = make_float2(h * (zk.x + zm.x),  h * (zk.y - zm.y));
        float2 G1 = make_float2(h * (zk.y + zm.y), -h * (zk.x - zm.x));
        if (p == 0) {
            float2 z2 = A[1024];
            float2 G0n = make_float2(2.0f * z2.x, 0.0f);   // G0[1024]
            float2 G1n = make_float2(2.0f * z2.y, 0.0f);   // G1[1024]
            B[0] = make_float2(G0.x + G0n.x, G0.y + G0n.y);
            B[1] = make_float2(G0.x - G0n.x, G0.y - G0n.y);
            C[0] = make_float2(G1.x + G1n.x, G1.y + G1n.y);
            C[1] = make_float2(G1.x - G1n.x, G1.y - G1n.y);
        } else {
            float2 wc = tw[p]; wc.y = -wc.y;
            B[2 * p]     = G0;
            B[2 * p + 1] = cmul(wc, G0);
            C[2 * p]     = G1;
            C[2 * p + 1] = cmul(wc, G1);
        }
    }
    __syncthreads();

    const float PH_SCALE = 683565275.57643158f;   // 2^31 / pi

    // inverse tail chain 0: result in A  -> theta ch0
    ifft_tail(B, A, tw, tid);
    unsigned* __restrict__ d0 = g_theta + (size_t)ch0 * S_LEN;
    for (int i = tid; i < S_LEN; i += FFT_THREADS) {
        float2 a = A[i];
        d0[i] = (unsigned)__float2int_rn(atan2f(a.y, a.x) * PH_SCALE);
    }
    __syncthreads();   // all reads of A done before chain 1 reuses buffers

    // inverse tail chain 1: result in B -> theta ch1
    ifft_tail(C, B, tw, tid);
    unsigned* __restrict__ d1 = d0 + S_LEN;
    for (int i = tid; i < S_LEN; i += FFT_THREADS) {
        float2 a = B[i];
        d1[i] = (unsigned)__float2int_rn(atan2f(a.y, a.x) * PH_SCALE);
    }
}

// ---------------------------------------------------------------------------
// Kernel 2: pairwise sign counting on integer phases + fused finalize.
// sign(sin(ti - tj)) == sign((int)(uti - utj)) where the subtraction is done
// in UNSIGNED arithmetic (wrap mod 2^32 == wrap mod 2pi is DEFINED behavior;
// a signed subtract here invites the compiler to fold "a-b>0" into "a>b",
// which drops the wrap — that was R3's bug).
// Lanes = samples; one ballot counts positives P; sumsign = 2P - S.
// Last block (threadfence + atomic gate) writes the output matrix.
// ---------------------------------------------------------------------------
__global__ __launch_bounds__(PLI_THREADS)
void pli_kernel(float* __restrict__ out) {
    __shared__ unsigned sth[NCH * CHUNK];             // 32 KB
    __shared__ int is_last;
    const int sc  = blockIdx.x;
    const int b   = blockIdx.y;
    const int tid = threadIdx.x;

    // stage CHUNK samples of all 64 channels (uint4 vectorized)
    const uint4* gsrc = reinterpret_cast<const uint4*>(g_theta);
    uint4* ssh = reinterpret_cast<uint4*>(sth);
    #pragma unroll
    for (int k = tid; k < NCH * (CHUNK / 4); k += PLI_THREADS) {
        int c  = k >> 5;                    // CHUNK/4 = 32 uint4 per channel
        int sp = k & 31;
        size_t gi = (((size_t)(b * NCH + c)) * S_LEN + (size_t)sc * CHUNK) / 4 + sp;
        ssh[k] = gsrc[gi];
    }
    __syncthreads();

    const int warp = tid >> 5;
    const int lane = tid & 31;

    for (int t = warp; t < 136; t += NWARPS) {
        int ti = 0, rem = t;
        while (rem >= (16 - ti)) { rem -= (16 - ti); ti++; }
        int tj = ti + rem;

        const unsigned* rowi = sth + (ti * 4) * CHUNK;
        const unsigned* rowj = sth + (tj * 4) * CHUNK;

        int acc[16];
        #pragma unroll
        for (int q = 0; q < 16; q++) acc[q] = 0;

        #pragma unroll
        for (int it = 0; it < CHUNK / 32; it++) {
            int s = it * 32 + lane;
            unsigned pi[4], pj[4];
            #pragma unroll
            for (int a = 0; a < 4; a++) pi[a] = rowi[a * CHUNK + s];
            #pragma unroll
            for (int a = 0; a < 4; a++) pj[a] = rowj[a * CHUNK + s];

            #pragma unroll
            for (int a = 0; a < 4; a++) {
                #pragma unroll
                for (int c2 = 0; c2 < 4; c2++) {
                    // UNSIGNED subtract: wrap mod 2^32 is defined; then
                    // two's-complement reinterpret for the sign test.
                    unsigned du = pi[a] - pj[c2];
                    unsigned m = __ballot_sync(0xffffffffu, (int)du > 0);
                    acc[a * 4 + c2] += __popc(m);
                }
            }
        }

        if (lane == 0) {
            #pragma unroll
            for (int a = 0; a < 4; a++)
                #pragma unroll
                for (int c2 = 0; c2 < 4; c2++)
                    atomicAdd(&g_cnt[(b * NCH + ti * 4 + a) * NCH + tj * 4 + c2],
                              acc[a * 4 + c2]);
        }
    }

    // ---- fused finalize: last block to finish writes the output ----
    __syncthreads();
    if (tid == 0) {
        __threadfence();
        int done = atomicAdd(&g_done, 1);
        is_last = (done == N_PLI_BLOCKS - 1);
    }
    __syncthreads();
    if (is_last) {
        __threadfence();
        for (int idx = tid; idx < NB * NCH * NCH; idx += PLI_THREADS) {
            int bb = idx >> 12;
            int i  = (idx >> 6) & 63;
            int j  = idx & 63;
            float v = 0.0f;
            if (i != j) {
                int c = (i < j) ? g_cnt[(bb * NCH + i) * NCH + j]
                                : g_cnt[(bb * NCH + j) * NCH + i];
                v = fabsf(2.0f * (float)c - (float)S_LEN) * (1.0f / (float)S_LEN);
            }
            out[idx] = v;
        }
    }
}

// ---------------------------------------------------------------------------
extern "C" void kernel_launch(void* const* d_in, const int* in_sizes, int n_in,
                              void* d_out, int out_size) {
    const float* x = (const float*)d_in[0];
    float* out = (float*)d_out;
    (void)in_sizes; (void)n_in; (void)out_size;

    const int fft_smem = (3 * 2048 + 1024) * (int)sizeof(float2);   // 57344 B
    cudaFuncSetAttribute(hilbert_kernel,
                         cudaFuncAttributeMaxDynamicSharedMemorySize, fft_smem);

    hilbert_kernel<<<NB * NCH / 2, FFT_THREADS, fft_smem>>>(x);
    pli_kernel<<<dim3(NSC, NB), PLI_THREADS>>>(out);
}